// round 2
// baseline (speedup 1.0000x reference)
#include <cuda_runtime.h>
#include <cuda_bf16.h>
#include <cstdint>

// ---------------------------------------------------------------------------
// MLPLinkPredictor: score[e] = W2 . relu(W1 [h[src];h[dst]] + b1) + b2
//
// Key identity: W1 [h_s; h_d] = W1a h_s + W1b h_d  (split W1 columns).
// => Precompute node projections C[n, 0:256] = h[n] @ W1a.T
//                                C[n, 256:512] = h[n] @ W1b.T
//    (one GEMM: 50000 x 512 x 256), then per edge a cheap gather + relu-dot.
// ---------------------------------------------------------------------------

#define N_NODES 50000
#define N_FEAT  256
#define N_OUT   512   // 2 * N_FEAT concatenated projections

// Scratch (device globals: allocation-free per harness rules)
__device__ float g_C[(size_t)N_NODES * N_OUT];   // 102.4 MB node projections
__device__ float g_Wt[(size_t)N_OUT * N_FEAT];   // 512 KB repacked weights

// ---------------------------------------------------------------------------
// Repack W1_w [256, 512] row-major into Wt [512, 256] with
//   Wt[j, k] = (j < 256) ? W1[j, k] : W1[j-256, 256 + k]
// so that C[n, j] = sum_k h[n,k] * Wt[j,k] gives the concat projection.
// ---------------------------------------------------------------------------
__global__ void repack_kernel(const float* __restrict__ W1) {
    int idx = blockIdx.x * blockDim.x + threadIdx.x;   // 0 .. 512*256-1
    if (idx >= N_OUT * N_FEAT) return;
    int j = idx / N_FEAT;
    int k = idx % N_FEAT;
    float v = (j < N_FEAT) ? W1[j * (2 * N_FEAT) + k]
                           : W1[(j - N_FEAT) * (2 * N_FEAT) + N_FEAT + k];
    g_Wt[idx] = v;
}

// ---------------------------------------------------------------------------
// GEMM: g_C[N_NODES, 512] = h[N_NODES, 256] @ g_Wt[512, 256]^T   (fp32)
// 128x128 tile, BK=8, 256 threads, 8x8 per thread.
// ---------------------------------------------------------------------------
#define BM 128
#define BN 128
#define BK 8
#define TM 8
#define TN 8

__global__ __launch_bounds__(256, 2)
void gemm_kernel(const float* __restrict__ h) {
    __shared__ float As[BK][BM];
    __shared__ float Bs[BK][BN];

    const int bn = blockIdx.x;           // 0..3   (512 / 128)
    const int bm = blockIdx.y;           // 0..390 (ceil(50000/128))
    const int tid = threadIdx.x;

    const int tm = (tid / 16) * TM;      // 0..120
    const int tn = (tid % 16) * TN;      // 0..120

    // Each thread loads one float4 of A tile and one of B tile per K step.
    const int ldRow  = tid >> 1;         // 0..127
    const int ldCol4 = (tid & 1) * 4;    // 0 or 4

    const int aRowG = bm * BM + ldRow;   // node row
    const int bRowG = bn * BN + ldRow;   // output-feature row (always < 512)

    float acc[TM][TN];
#pragma unroll
    for (int i = 0; i < TM; i++)
#pragma unroll
        for (int j = 0; j < TN; j++) acc[i][j] = 0.f;

    for (int k0 = 0; k0 < N_FEAT; k0 += BK) {
        float4 av = make_float4(0.f, 0.f, 0.f, 0.f);
        if (aRowG < N_NODES)
            av = *reinterpret_cast<const float4*>(&h[(size_t)aRowG * N_FEAT + k0 + ldCol4]);
        As[ldCol4 + 0][ldRow] = av.x;
        As[ldCol4 + 1][ldRow] = av.y;
        As[ldCol4 + 2][ldRow] = av.z;
        As[ldCol4 + 3][ldRow] = av.w;

        float4 bv = *reinterpret_cast<const float4*>(&g_Wt[(size_t)bRowG * N_FEAT + k0 + ldCol4]);
        Bs[ldCol4 + 0][ldRow] = bv.x;
        Bs[ldCol4 + 1][ldRow] = bv.y;
        Bs[ldCol4 + 2][ldRow] = bv.z;
        Bs[ldCol4 + 3][ldRow] = bv.w;

        __syncthreads();

#pragma unroll
        for (int k = 0; k < BK; k++) {
            float a[TM], b[TN];
#pragma unroll
            for (int i = 0; i < TM; i++) a[i] = As[k][tm + i];
#pragma unroll
            for (int j = 0; j < TN; j++) b[j] = Bs[k][tn + j];
#pragma unroll
            for (int i = 0; i < TM; i++)
#pragma unroll
                for (int j = 0; j < TN; j++)
                    acc[i][j] = fmaf(a[i], b[j], acc[i][j]);
        }
        __syncthreads();
    }

#pragma unroll
    for (int i = 0; i < TM; i++) {
        int r = bm * BM + tm + i;
        if (r >= N_NODES) break;
        float* crow = &g_C[(size_t)r * N_OUT + bn * BN + tn];
#pragma unroll
        for (int j = 0; j < TN; j += 4) {
            float4 v = make_float4(acc[i][j], acc[i][j + 1], acc[i][j + 2], acc[i][j + 3]);
            *reinterpret_cast<float4*>(&crow[j]) = v;
        }
    }
}

// ---------------------------------------------------------------------------
// Edge kernel: one warp per edge.
//   hid[j] = relu(C[src, j] + C[dst, 256 + j] + b1[j]),  j in [0,256)
//   out[e] = dot(hid, W2) + b2
// Each lane handles 2 float4 chunks (coalesced), warp shuffle reduce.
// ---------------------------------------------------------------------------
__global__ __launch_bounds__(256)
void edge_kernel(const int* __restrict__ src, const int* __restrict__ dst,
                 const float* __restrict__ b1, const float* __restrict__ W2w,
                 const float* __restrict__ W2b, float* __restrict__ out, int E) {
    int warp = (blockIdx.x * blockDim.x + threadIdx.x) >> 5;
    int lane = threadIdx.x & 31;
    if (warp >= E) return;

    int s = src[warp];
    int d = dst[warp];

    const float4* Cs = reinterpret_cast<const float4*>(g_C + (size_t)s * N_OUT);          // first 256
    const float4* Cd = reinterpret_cast<const float4*>(g_C + (size_t)d * N_OUT + N_FEAT); // second 256
    const float4* B1 = reinterpret_cast<const float4*>(b1);
    const float4* W2 = reinterpret_cast<const float4*>(W2w);

    float acc = 0.f;
#pragma unroll
    for (int p = 0; p < 2; p++) {
        int i = p * 32 + lane;          // float4 index 0..63 over 256 floats
        float4 a  = Cs[i];
        float4 b  = Cd[i];
        float4 bb = B1[i];
        float4 w  = W2[i];
        float h0 = fmaxf(a.x + b.x + bb.x, 0.f);
        float h1 = fmaxf(a.y + b.y + bb.y, 0.f);
        float h2 = fmaxf(a.z + b.z + bb.z, 0.f);
        float h3 = fmaxf(a.w + b.w + bb.w, 0.f);
        acc = fmaf(h0, w.x, acc);
        acc = fmaf(h1, w.y, acc);
        acc = fmaf(h2, w.z, acc);
        acc = fmaf(h3, w.w, acc);
    }

#pragma unroll
    for (int off = 16; off; off >>= 1)
        acc += __shfl_down_sync(0xffffffffu, acc, off);

    if (lane == 0) out[warp] = acc + W2b[0];
}

// ---------------------------------------------------------------------------
extern "C" void kernel_launch(void* const* d_in, const int* in_sizes, int n_in,
                              void* d_out, int out_size) {
    const float* h    = (const float*)d_in[0];
    const int*   src  = (const int*)  d_in[1];
    const int*   dst  = (const int*)  d_in[2];
    const float* W1w  = (const float*)d_in[3];
    const float* W1b  = (const float*)d_in[4];
    const float* W2w  = (const float*)d_in[5];
    const float* W2b  = (const float*)d_in[6];
    float* out = (float*)d_out;

    const int E = in_sizes[1];   // 800000 edges

    // 1) Repack weights
    repack_kernel<<<(N_OUT * N_FEAT + 255) / 256, 256>>>(W1w);

    // 2) Node projection GEMM: g_C = h @ Wt^T  (50000 x 512 x 256)
    dim3 ggrid(N_OUT / BN, (N_NODES + BM - 1) / BM);
    gemm_kernel<<<ggrid, 256>>>(h);

    // 3) Per-edge gather + relu-dot
    int warpsPerBlock = 256 / 32;
    int eblocks = (E + warpsPerBlock - 1) / warpsPerBlock;
    edge_kernel<<<eblocks, 256>>>(src, dst, W1b, W2w, W2b, out, E);
}